// round 12
// baseline (speedup 1.0000x reference)
#include <cuda_runtime.h>
#include <cuda_fp16.h>
#include <cstdint>

// FMHA via mma.sync.m16n8k16 (fp16 in, f32 accum), cp.async double-buffered.
// R10: softmax dependency chain hidden under MMA issue:
//  - approx row max computed from Khi passes only (exact-math shift), its
//    shuffle chain overlaps the Klo MMA pass
//  - oacc rescale issued before the Klo pass (interleaves with MMA)
//  - row-sum shuffles moved after PV issue
// B=16, N=2048, D=128. BM=64, BN=64, 128 threads, 2 CTAs/SM.

#define NTH 128
#define TOT (16 * 2048 * 128)
#define LOG2E 1.4426950408889634f

__device__ uint2 g_khi[TOT / 4];
__device__ uint2 g_klo[TOT / 4];
__device__ uint2 g_vh [TOT / 4];

__device__ __forceinline__ uint32_t sptr(const void* p) {
    return (uint32_t)__cvta_generic_to_shared(p);
}
__device__ __forceinline__ float f16r(float x) {
    return __half2float(__float2half_rn(x));
}
__device__ __forceinline__ uint32_t pkh(float a, float b) {
    __half2 h = __floats2half2_rn(a, b);
    return *reinterpret_cast<const uint32_t*>(&h);
}
__device__ __forceinline__ float ex2(float x) {
    float y;
    asm("ex2.approx.f32 %0, %1;" : "=f"(y) : "f"(x));
    return y;
}
__device__ __forceinline__ void mma16816(float* c, uint32_t a0, uint32_t a1,
                                         uint32_t a2, uint32_t a3,
                                         uint32_t b0, uint32_t b1) {
    asm volatile(
        "mma.sync.aligned.m16n8k16.row.col.f32.f16.f16.f32 "
        "{%0,%1,%2,%3}, {%4,%5,%6,%7}, {%8,%9}, {%0,%1,%2,%3};"
        : "+f"(c[0]), "+f"(c[1]), "+f"(c[2]), "+f"(c[3])
        : "r"(a0), "r"(a1), "r"(a2), "r"(a3), "r"(b0), "r"(b1));
}
__device__ __forceinline__ void ldsm4(uint32_t* r, uint32_t addr) {
    asm volatile("ldmatrix.sync.aligned.m8n8.x4.shared.b16 {%0,%1,%2,%3}, [%4];"
                 : "=r"(r[0]), "=r"(r[1]), "=r"(r[2]), "=r"(r[3]) : "r"(addr));
}
__device__ __forceinline__ void ldsm4t(uint32_t* r, uint32_t addr) {
    asm volatile("ldmatrix.sync.aligned.m8n8.x4.trans.shared.b16 {%0,%1,%2,%3}, [%4];"
                 : "=r"(r[0]), "=r"(r[1]), "=r"(r[2]), "=r"(r[3]) : "r"(addr));
}
#define CP16(dst, src) \
    asm volatile("cp.async.cg.shared.global [%0], [%1], 16;" :: "r"(dst), "l"(src))
#define CP_COMMIT() asm volatile("cp.async.commit_group;" ::: "memory")
#define CP_WAIT1()  asm volatile("cp.async.wait_group 1;" ::: "memory")

// ---- pre-pass: k -> (khi, klo) scaled by log2e, v -> vh ----
__global__ __launch_bounds__(256)
void prep_kernel(const float* __restrict__ k, const float* __restrict__ v) {
    int i = blockIdx.x * 256 + threadIdx.x;
    const float4* k4 = (const float4*)k;
    const float4* v4 = (const float4*)v;
    float4 kk = k4[i];
    float x0 = kk.x * LOG2E, x1 = kk.y * LOG2E, x2 = kk.z * LOG2E, x3 = kk.w * LOG2E;
    float h0 = f16r(x0), h1 = f16r(x1), h2 = f16r(x2), h3 = f16r(x3);
    g_khi[i] = make_uint2(pkh(h0, h1), pkh(h2, h3));
    g_klo[i] = make_uint2(pkh(x0 - h0, x1 - h1), pkh(x2 - h2, x3 - h3));
    float4 vv = v4[i];
    g_vh[i] = make_uint2(pkh(vv.x, vv.y), pkh(vv.z, vv.w));
}

#define STAGE_BYTES 49152
#define OFF_KLO 16384
#define OFF_V   32768

__global__ __launch_bounds__(NTH, 2)
void fa_mma_kernel(const float* __restrict__ q, float* __restrict__ out) {
    extern __shared__ char smem[];
    const uint32_t smemB = sptr(smem);

    const int tid  = threadIdx.x;
    const int w    = tid >> 5;
    const int lane = tid & 31;
    const int g    = lane >> 2;
    const int tig  = lane & 3;
    const int rloc = ((lane >> 4) << 3) | (lane & 7);
    const int chalf = (lane >> 3) & 1;
    const int lan7  = lane & 7;

    const int bid = blockIdx.x;
    const int b = bid >> 5, qt = bid & 31;

    const float* qg = q + ((size_t)(b * 2048 + qt * 64)) * 128;
    float*       og = out + ((size_t)(b * 2048 + qt * 64)) * 128;

    const size_t gkhi = (size_t)__cvta_generic_to_global(g_khi);
    const size_t gklo = (size_t)__cvta_generic_to_global(g_klo);
    const size_t gvh  = (size_t)__cvta_generic_to_global(g_vh);

    const int kbyte_base = b * 2048 * 256;

    // ---- issue tiles 0 and 1 while loading Q frags ----
    #pragma unroll
    for (int st = 0; st < 2; st++) {
        uint32_t sb = smemB + st * STAGE_BYTES;
        int tbase = kbyte_base + st * 64 * 256;
        #pragma unroll
        for (int it = 0; it < 8; it++) {
            int idx8 = tid + it * NTH;
            int r = idx8 >> 4, c = idx8 & 15;
            uint32_t doff = (uint32_t)((r * 16 + (c ^ (r & 7))) * 16);
            size_t soff = (size_t)(tbase + idx8 * 16);
            CP16(sb + doff,           gkhi + soff);
            CP16(sb + OFF_KLO + doff, gklo + soff);
            CP16(sb + OFF_V + doff,   gvh + soff);
        }
        CP_COMMIT();
    }

    // ---- Q fragments in registers (hi/lo fp16 split; K carries log2e) ----
    uint32_t qh[8][4], ql[8][4];
    {
        const float* qr0 = qg + (size_t)(w * 16 + g) * 128;
        const float* qr1 = qr0 + 8 * 128;
        #pragma unroll
        for (int ks = 0; ks < 8; ks++) {
            #pragma unroll
            for (int j = 0; j < 2; j++) {
                int col = ks * 16 + j * 8 + tig * 2;
                float x0 = qr0[col], x1 = qr0[col + 1];
                float y0 = qr1[col], y1 = qr1[col + 1];
                float hx0 = f16r(x0), hx1 = f16r(x1);
                float hy0 = f16r(y0), hy1 = f16r(y1);
                qh[ks][2 * j]     = pkh(hx0, hx1);
                qh[ks][2 * j + 1] = pkh(hy0, hy1);
                ql[ks][2 * j]     = pkh(x0 - hx0, x1 - hx1);
                ql[ks][2 * j + 1] = pkh(y0 - hy0, y1 - hy1);
            }
        }
    }

    float oacc[16][4];
    #pragma unroll
    for (int nb = 0; nb < 16; nb++)
        #pragma unroll
        for (int j = 0; j < 4; j++) oacc[nb][j] = 0.f;
    float m0 = -1e30f, m1 = -1e30f, l0 = 0.f, l1 = 0.f;

    for (int kt = 0; kt < 32; kt++) {
        CP_WAIT1();
        __syncthreads();

        const uint32_t sb    = smemB + (kt & 1) * STAGE_BYTES;
        const uint32_t sKhiB = sb;
        const uint32_t sKloB = sb + OFF_KLO;
        const uint32_t sVB   = sb + OFF_V;

        float sacc[8][4];
        #pragma unroll
        for (int nb = 0; nb < 8; nb++)
            #pragma unroll
            for (int j = 0; j < 4; j++) sacc[nb][j] = 0.f;

        // ---- loop A: Khi passes (qh*Khi + ql*Khi) ----
        #pragma unroll
        for (int ks = 0; ks < 8; ks++) {
            uint32_t kb[16];
            int crow = 2 * ks + chalf;
            #pragma unroll
            for (int np = 0; np < 4; np++) {
                int row = np * 16 + rloc;
                ldsm4(kb + np * 4, sKhiB + row * 256 + ((crow ^ (row & 7)) << 4));
            }
            #pragma unroll
            for (int nb = 0; nb < 8; nb++) {
                mma16816(sacc[nb], qh[ks][0], qh[ks][1], qh[ks][2], qh[ks][3],
                         kb[nb * 2], kb[nb * 2 + 1]);
                mma16816(sacc[nb], ql[ks][0], ql[ks][1], ql[ks][2], ql[ks][3],
                         kb[nb * 2], kb[nb * 2 + 1]);
            }
        }

        // ---- approx row max from Khi-only scores (error ~2e-3 log2 units;
        //      mathematically exact as a softmax shift). Shuffle chain below
        //      overlaps with loop B's MMA issue. ----
        float tm0 = -1e30f, tm1 = -1e30f;
        #pragma unroll
        for (int nb = 0; nb < 8; nb++) {
            tm0 = fmaxf(tm0, fmaxf(sacc[nb][0], sacc[nb][1]));
            tm1 = fmaxf(tm1, fmaxf(sacc[nb][2], sacc[nb][3]));
        }
        tm0 = fmaxf(tm0, __shfl_xor_sync(0xffffffffu, tm0, 1));
        tm0 = fmaxf(tm0, __shfl_xor_sync(0xffffffffu, tm0, 2));
        tm1 = fmaxf(tm1, __shfl_xor_sync(0xffffffffu, tm1, 1));
        tm1 = fmaxf(tm1, __shfl_xor_sync(0xffffffffu, tm1, 2));
        float mn0 = fmaxf(m0, tm0), mn1 = fmaxf(m1, tm1);
        float sc0 = ex2(m0 - mn0), sc1 = ex2(m1 - mn1);

        // ---- rescale O (interleaves with loop B MMA issue) ----
        #pragma unroll
        for (int nb = 0; nb < 16; nb++) {
            oacc[nb][0] *= sc0; oacc[nb][1] *= sc0;
            oacc[nb][2] *= sc1; oacc[nb][3] *= sc1;
        }

        // ---- loop B: Klo pass (qh*Klo) ----
        #pragma unroll
        for (int ks = 0; ks < 8; ks++) {
            uint32_t kb[16];
            int crow = 2 * ks + chalf;
            #pragma unroll
            for (int np = 0; np < 4; np++) {
                int row = np * 16 + rloc;
                ldsm4(kb + np * 4, sKloB + row * 256 + ((crow ^ (row & 7)) << 4));
            }
            #pragma unroll
            for (int nb = 0; nb < 8; nb++)
                mma16816(sacc[nb], qh[ks][0], qh[ks][1], qh[ks][2], qh[ks][3],
                         kb[nb * 2], kb[nb * 2 + 1]);
        }

        // ---- P = 2^(S - mn), pack straight into PV A-fragments ----
        uint32_t pf[8][2];
        float s0 = 0.f, s1 = 0.f;
        #pragma unroll
        for (int nb = 0; nb < 8; nb++) {
            float p0 = ex2(sacc[nb][0] - mn0);
            float p1 = ex2(sacc[nb][1] - mn0);
            float p2 = ex2(sacc[nb][2] - mn1);
            float p3 = ex2(sacc[nb][3] - mn1);
            s0 += p0 + p1;
            s1 += p2 + p3;
            pf[nb][0] = pkh(p0, p1);
            pf[nb][1] = pkh(p2, p3);
        }
        m0 = mn0;
        m1 = mn1;

        // ---- O += P V (issues before the sum shuffle chain) ----
        #pragma unroll
        for (int ks = 0; ks < 4; ks++) {
            uint32_t a0 = pf[2 * ks][0], a1 = pf[2 * ks][1];
            uint32_t a2 = pf[2 * ks + 1][0], a3 = pf[2 * ks + 1][1];
            int vrow = ks * 16 + chalf * 8 + lan7;
            uint32_t vbase = sVB + vrow * 256;
            int vsw = vrow & 7;
            #pragma unroll
            for (int np = 0; np < 8; np++) {
                uint32_t vb[4];
                int vc = 2 * np + (lane >> 4);
                ldsm4t(vb, vbase + ((vc ^ vsw) << 4));
                mma16816(oacc[2 * np],     a0, a1, a2, a3, vb[0], vb[1]);
                mma16816(oacc[2 * np + 1], a0, a1, a2, a3, vb[2], vb[3]);
            }
        }

        // ---- row-sum shuffles + l update (off the PV critical path) ----
        s0 += __shfl_xor_sync(0xffffffffu, s0, 1);
        s0 += __shfl_xor_sync(0xffffffffu, s0, 2);
        s1 += __shfl_xor_sync(0xffffffffu, s1, 1);
        s1 += __shfl_xor_sync(0xffffffffu, s1, 2);
        l0 = l0 * sc0 + s0;
        l1 = l1 * sc1 + s1;

        __syncthreads();

        // ---- prefetch tile kt+2 into buf[kt&1] ----
        if (kt + 2 < 32) {
            uint32_t pb = smemB + (kt & 1) * STAGE_BYTES;
            int tbase = kbyte_base + (kt + 2) * 64 * 256;
            #pragma unroll
            for (int it = 0; it < 8; it++) {
                int idx8 = tid + it * NTH;
                int r = idx8 >> 4, c = idx8 & 15;
                uint32_t doff = (uint32_t)((r * 16 + (c ^ (r & 7))) * 16);
                size_t soff = (size_t)(tbase + idx8 * 16);
                CP16(pb + doff,           gkhi + soff);
                CP16(pb + OFF_KLO + doff, gklo + soff);
                CP16(pb + OFF_V + doff,   gvh + soff);
            }
        }
        CP_COMMIT();
    }

    // ---- epilogue ----
    float inv0 = 1.0f / l0, inv1 = 1.0f / l1;
    float* o0 = og + (size_t)(w * 16 + g) * 128;
    float* o1 = o0 + 8 * 128;
    #pragma unroll
    for (int nb = 0; nb < 16; nb++) {
        int col = nb * 8 + tig * 2;
        *(float2*)(o0 + col) = make_float2(oacc[nb][0] * inv0, oacc[nb][1] * inv0);
        *(float2*)(o1 + col) = make_float2(oacc[nb][2] * inv1, oacc[nb][3] * inv1);
    }
}

extern "C" void kernel_launch(void* const* d_in, const int* in_sizes, int n_in,
                              void* d_out, int out_size) {
    const float* q = (const float*)d_in[0];
    const float* k = (const float*)d_in[1];
    const float* v = (const float*)d_in[2];
    float* out = (float*)d_out;

    prep_kernel<<<TOT / 4 / 256, 256>>>(k, v);

    cudaFuncSetAttribute(fa_mma_kernel,
                         cudaFuncAttributeMaxDynamicSharedMemorySize,
                         2 * STAGE_BYTES);
    fa_mma_kernel<<<512, NTH, 2 * STAGE_BYTES>>>(q, out);
}